// round 14
// baseline (speedup 1.0000x reference)
#include <cuda_runtime.h>
#include <math.h>
#include <stdint.h>

// Problem dims (fixed by the dataset)
#define B_   2
#define S_   2048
#define D_   1024
#define D2_  512      // f16x2 pairs per row
#define H_   16
#define DK_  64
#define DK2_ 32
#define MTOT (B_ * S_)

// ---------------------------------------------------------------------------
// Scratch (f16x2 pairs stored as uint32)
// ---------------------------------------------------------------------------
__device__ uint32_t g_qin[MTOT * D2_];          // packed inputs
__device__ uint32_t g_kin[MTOT * D2_];
__device__ uint32_t g_vin[MTOT * D2_];
__device__ uint32_t g_q[B_ * H_ * S_ * DK2_];   // packed head-layout activations
__device__ uint32_t g_k[B_ * H_ * S_ * DK2_];
__device__ uint32_t g_v[B_ * H_ * S_ * DK2_];
__device__ uint32_t g_att[B_ * H_ * S_ * DK2_];
__device__ uint32_t g_wq[D2_ * D_];             // k-pair-packed weights: [k2][n]
__device__ uint32_t g_wk[D2_ * D_];
__device__ uint32_t g_wv[D2_ * D_];
__device__ uint32_t g_wo[D2_ * D_];

// f16x2 pack: h0 = lo, h1 = hi  (cvt d,a,b -> d.h1=a, d.h0=b)
__device__ __forceinline__ uint32_t f2h2(float lo, float hi) {
    uint32_t r;
    asm("cvt.rn.f16x2.f32 %0, %1, %2;" : "=r"(r) : "f"(hi), "f"(lo));
    return r;
}

__device__ __forceinline__ void mma_f16(float* d, const uint32_t* a, const uint32_t* b) {
    asm volatile(
        "mma.sync.aligned.m16n8k16.row.col.f32.f16.f16.f32 "
        "{%0,%1,%2,%3}, {%4,%5,%6,%7}, {%8,%9}, {%0,%1,%2,%3};"
        : "+f"(d[0]), "+f"(d[1]), "+f"(d[2]), "+f"(d[3])
        : "r"(a[0]), "r"(a[1]), "r"(a[2]), "r"(a[3]), "r"(b[0]), "r"(b[1]));
}

__device__ __forceinline__ uint32_t smem_u32(const void* p) {
    return (uint32_t)__cvta_generic_to_shared(p);
}
__device__ __forceinline__ void cp_async16(uint32_t dst, const void* src) {
    asm volatile("cp.async.cg.shared.global [%0], [%1], 16;\n" :: "r"(dst), "l"(src));
}
__device__ __forceinline__ void cp_commit() {
    asm volatile("cp.async.commit_group;\n");
}
template <int N>
__device__ __forceinline__ void cp_wait() {
    asm volatile("cp.async.wait_group %0;\n" :: "n"(N));
}

// ---------------------------------------------------------------------------
// Pre-conversion kernels (once per launch) — unchanged from R13
// ---------------------------------------------------------------------------
__global__ __launch_bounds__(256)
void cvt_inputs(const float* __restrict__ q, const float* __restrict__ k,
                const float* __restrict__ v) {
    const int z = blockIdx.y;
    const float* src = (z == 0) ? q : (z == 1) ? k : v;
    uint32_t*    dst = (z == 0) ? g_qin : (z == 1) ? g_kin : g_vin;
    const int i = blockIdx.x * 256 + threadIdx.x;
    float4 x = ((const float4*)src)[i];
    uint2 o;
    o.x = f2h2(x.x, x.y);
    o.y = f2h2(x.z, x.w);
    ((uint2*)dst)[i] = o;
}

__global__ __launch_bounds__(256)
void cvt_weights(const float* __restrict__ wq, const float* __restrict__ wk,
                 const float* __restrict__ wv, const float* __restrict__ wo) {
    const int z = blockIdx.y;
    const float* w = (z == 0) ? wq : (z == 1) ? wk : (z == 2) ? wv : wo;
    uint32_t*  dst = (z == 0) ? g_wq : (z == 1) ? g_wk : (z == 2) ? g_wv : g_wo;
    const int idx = blockIdx.x * 256 + threadIdx.x;
    const int k2 = idx >> 8;
    const int n4 = (idx & 255) * 4;
    float4 r0 = *(const float4*)&w[(size_t)(2 * k2)     * D_ + n4];
    float4 r1 = *(const float4*)&w[(size_t)(2 * k2 + 1) * D_ + n4];
    uint4 o;
    o.x = f2h2(r0.x, r1.x);
    o.y = f2h2(r0.y, r1.y);
    o.z = f2h2(r0.z, r1.z);
    o.w = f2h2(r0.w, r1.w);
    *(uint4*)&dst[(size_t)k2 * D_ + n4] = o;
}

// ---------------------------------------------------------------------------
// FP16 GEMM body — unchanged from R13
// ---------------------------------------------------------------------------
#define GBM 128
#define GBN 128
#define GBK2 8
#define AST 12
#define BST 136

template <bool HEAD_OUT>
__device__ __forceinline__ void gemm_body(
    const uint32_t* __restrict__ A, const uint32_t* __restrict__ W,
    const float* __restrict__ bias, void* __restrict__ Cv) {

    __shared__ uint32_t As[2][GBM][AST];
    __shared__ uint32_t Bs[2][GBK2][BST];

    const int tid   = threadIdx.x;
    const int wid   = tid >> 5;
    const int lane  = tid & 31;
    const int g     = lane >> 2;
    const int tig   = lane & 3;

    const int warp_m = wid & 3;
    const int warp_n = wid >> 2;

    const int row0 = blockIdx.y * GBM;
    const int col0 = blockIdx.x * GBN;

    const int a_r = tid >> 1, a_c = (tid & 1) * 4;
    const int b_r = tid >> 5, b_c = (tid & 31) * 4;

    auto issue_tile = [&](int kt2, int buf) {
        cp_async16(smem_u32(&As[buf][a_r][a_c]),
                   &A[(size_t)(row0 + a_r) * D2_ + kt2 + a_c]);
        cp_async16(smem_u32(&Bs[buf][b_r][b_c]),
                   &W[(size_t)(kt2 + b_r) * D_ + col0 + b_c]);
        cp_commit();
    };

    float acc[2][8][4];
#pragma unroll
    for (int mt = 0; mt < 2; mt++)
#pragma unroll
        for (int nt = 0; nt < 8; nt++)
#pragma unroll
            for (int i = 0; i < 4; i++) acc[mt][nt][i] = 0.0f;

    const int NT = D2_ / GBK2;
    issue_tile(0, 0);

    for (int it = 0; it < NT; it++) {
        const int buf = it & 1;
        cp_wait<0>();
        __syncthreads();
        if (it + 1 < NT)
            issue_tile((it + 1) * GBK2, buf ^ 1);

        uint32_t afr[2][4], bfr[8][2];
#pragma unroll
        for (int mt = 0; mt < 2; mt++) {
            const int r0 = warp_m * 32 + mt * 16;
            afr[mt][0] = As[buf][r0 + g    ][tig    ];
            afr[mt][1] = As[buf][r0 + g + 8][tig    ];
            afr[mt][2] = As[buf][r0 + g    ][tig + 4];
            afr[mt][3] = As[buf][r0 + g + 8][tig + 4];
        }
#pragma unroll
        for (int nt = 0; nt < 8; nt++) {
            const int n0 = warp_n * 64 + nt * 8;
            bfr[nt][0] = Bs[buf][tig    ][n0 + g];
            bfr[nt][1] = Bs[buf][tig + 4][n0 + g];
        }
#pragma unroll
        for (int mt = 0; mt < 2; mt++)
#pragma unroll
            for (int nt = 0; nt < 8; nt++)
                mma_f16(acc[mt][nt], afr[mt], bfr[nt]);
    }

#pragma unroll
    for (int mt = 0; mt < 2; mt++) {
#pragma unroll
        for (int nt = 0; nt < 8; nt++) {
            const int cbase = col0 + warp_n * 64 + nt * 8 + tig * 2;
#pragma unroll
            for (int half = 0; half < 2; half++) {
                const int r = row0 + warp_m * 32 + mt * 16 + g + half * 8;
                const float v0 = acc[mt][nt][half * 2 + 0] + bias[cbase];
                const float v1 = acc[mt][nt][half * 2 + 1] + bias[cbase + 1];
                if (HEAD_OUT) {
                    const int b = r / S_, s = r % S_;
                    const int hh = cbase / DK_, d = cbase % DK_;
                    ((uint32_t*)Cv)[(((size_t)(b * H_ + hh)) * S_ + s) * DK2_ + (d >> 1)] =
                        f2h2(v0, v1);
                } else {
                    ((float*)Cv)[(size_t)r * D_ + cbase    ] = v0;
                    ((float*)Cv)[(size_t)r * D_ + cbase + 1] = v1;
                }
            }
        }
    }
}

__global__ __launch_bounds__(256, 2)
void qkv_gemm(const float* __restrict__ bq, const float* __restrict__ bk,
              const float* __restrict__ bv) {
    const int z = blockIdx.z;
    const uint32_t* A    = (z == 0) ? g_qin : (z == 1) ? g_kin : g_vin;
    const uint32_t* W    = (z == 0) ? g_wq  : (z == 1) ? g_wk  : g_wv;
    const float*    bias = (z == 0) ? bq    : (z == 1) ? bk    : bv;
    uint32_t*       C    = (z == 0) ? g_q   : (z == 1) ? g_k   : g_v;
    gemm_body<true>(A, W, bias, C);
}

__global__ __launch_bounds__(256, 2)
void out_gemm(const float* __restrict__ bias, float* __restrict__ C) {
    gemm_body<false>(g_att, g_wo, bias, C);
}

// ---------------------------------------------------------------------------
// FP16 flash attention (causal): BQ=128, 256 threads (8 warps x 16 q-rows).
// K/V load + repack amortized over 2x q-rows; per-warp early-exit on fully
// masked key blocks (barriers stay uniform). Per-row math identical to R13.
// ---------------------------------------------------------------------------
#define BQ   128
#define BKA  32
#define KST  36   // K B-frag banks 4g+tig distinct
#define VRST 36   // raw V tile (d-packed)
#define VST  72   // V B-frag banks 8tig+g distinct; 64 d-cols fit
#define PST  20   // P A-frag banks 20g+tig distinct

__global__ __launch_bounds__(256, 2)
void attn_tc() {
    __shared__ uint32_t Ks[2][BKA][KST];     //  9216 B
    __shared__ uint32_t Vraw[2][BKA][VRST];  //  9216 B
    __shared__ uint32_t Vpk[2][16][VST];     //  9216 B
    __shared__ uint32_t Ps[BQ][PST];         // 10240 B  (47888 total)

    const int tid  = threadIdx.x;
    const int warp = tid >> 5;   // 0..7
    const int lane = tid & 31;
    const int g    = lane >> 2;
    const int tig  = lane & 3;

    const int qi = blockIdx.x;
    const int h  = blockIdx.y;
    const int b  = blockIdx.z;
    const size_t base = (size_t)(b * H_ + h) * S_ * DK2_;
    const uint32_t* Kp = g_k + base;
    const uint32_t* Vp = g_v + base;

    const int q0   = qi * BQ;
    const int r_lo = q0 + warp * 16 + g;
    const int r_hi = r_lo + 8;
    const int wmax = q0 + warp * 16 + 15;   // last q-row owned by this warp

    // Q fragments: 4 k16-chunks over DK=64
    uint32_t qf[4][4];
    {
        const uint32_t* Qb = g_q + base + (size_t)(q0 + warp * 16) * DK2_;
#pragma unroll
        for (int kc = 0; kc < 4; kc++) {
            qf[kc][0] = Qb[(size_t)g       * DK2_ + kc * 8 + tig    ];
            qf[kc][1] = Qb[(size_t)(g + 8) * DK2_ + kc * 8 + tig    ];
            qf[kc][2] = Qb[(size_t)g       * DK2_ + kc * 8 + tig + 4];
            qf[kc][3] = Qb[(size_t)(g + 8) * DK2_ + kc * 8 + tig + 4];
        }
    }

    // K/V tile: 32 rows x 32 u32 = 256 16B-chunks per tensor; 256 thr -> 1 each
    auto issue_kv = [&](int kb, int buf) {
        const int k0 = kb * BKA;
        const int r  = tid >> 3;          // 0..31
        const int c4 = (tid & 7) * 4;     // 0..28
        cp_async16(smem_u32(&Ks[buf][r][c4]),   &Kp[(size_t)(k0 + r) * DK2_ + c4]);
        cp_async16(smem_u32(&Vraw[buf][r][c4]), &Vp[(size_t)(k0 + r) * DK2_ + c4]);
        cp_commit();
    };

    float m_i[2] = {-1e30f, -1e30f};
    float l_i[2] = {0.0f, 0.0f};
    float o_acc[8][4];
#pragma unroll
    for (int nt = 0; nt < 8; nt++)
#pragma unroll
        for (int i = 0; i < 4; i++) o_acc[nt][i] = 0.0f;

    const float scale = 0.125f;
    const int nkb = (q0 + BQ) / BKA;

    issue_kv(0, 0);

    for (int kb = 0; kb < nkb; kb++) {
        const int k0  = kb * BKA;
        const int buf = kb & 1;
        cp_wait<0>();
        __syncthreads();
        if (kb + 1 < nkb)
            issue_kv(kb + 1, buf ^ 1);

        // ---- repack V (all threads): 512 items / 256 thr = 2 each ----
#pragma unroll
        for (int i = 0; i < 2; i++) {
            const int c  = tid + i * 256;     // 0..511
            const int k2 = c >> 5, d2 = c & 31;
            const uint32_t lo = Vraw[buf][2 * k2    ][d2];
            const uint32_t hi = Vraw[buf][2 * k2 + 1][d2];
            uint32_t e, o;
            asm("prmt.b32 %0, %1, %2, 0x5410;" : "=r"(e) : "r"(lo), "r"(hi));
            asm("prmt.b32 %0, %1, %2, 0x7632;" : "=r"(o) : "r"(lo), "r"(hi));
            Vpk[buf][k2][2 * d2    ] = e;
            Vpk[buf][k2][2 * d2 + 1] = o;
        }

        const bool active = (k0 <= wmax);   // any unmasked key for this warp?
        float s[4][4];

        if (active) {
            // ---- S = Q @ K^T ----
#pragma unroll
            for (int nt = 0; nt < 4; nt++)
#pragma unroll
                for (int i = 0; i < 4; i++) s[nt][i] = 0.0f;

#pragma unroll
            for (int kc = 0; kc < 4; kc++) {
                uint32_t bf[4][2];
#pragma unroll
                for (int nt = 0; nt < 4; nt++) {
                    bf[nt][0] = Ks[buf][nt * 8 + g][kc * 8 + tig    ];
                    bf[nt][1] = Ks[buf][nt * 8 + g][kc * 8 + tig + 4];
                }
#pragma unroll
                for (int nt = 0; nt < 4; nt++)
                    mma_f16(s[nt], qf[kc], bf[nt]);
            }

            // ---- scale + causal mask + online softmax ----
#pragma unroll
            for (int half = 0; half < 2; half++) {
                const int qg = (half == 0) ? r_lo : r_hi;
                float mx = -1e30f;
#pragma unroll
                for (int nt = 0; nt < 4; nt++) {
#pragma unroll
                    for (int cc = 0; cc < 2; cc++) {
                        const int kg = k0 + nt * 8 + tig * 2 + cc;
                        float sv = s[nt][half * 2 + cc] * scale;
                        if (kg > qg) sv = -1e30f;
                        s[nt][half * 2 + cc] = sv;
                        mx = fmaxf(mx, sv);
                    }
                }
                mx = fmaxf(mx, __shfl_xor_sync(0xffffffffu, mx, 1));
                mx = fmaxf(mx, __shfl_xor_sync(0xffffffffu, mx, 2));

                const float mnew = fmaxf(m_i[half], mx);
                const float corr = __expf(m_i[half] - mnew);
                m_i[half] = mnew;

                float ssum = 0.0f;
#pragma unroll
                for (int nt = 0; nt < 4; nt++) {
#pragma unroll
                    for (int cc = 0; cc < 2; cc++) {
                        const float p = __expf(s[nt][half * 2 + cc] - mnew);
                        s[nt][half * 2 + cc] = p;
                        ssum += p;
                    }
                }
                ssum += __shfl_xor_sync(0xffffffffu, ssum, 1);
                ssum += __shfl_xor_sync(0xffffffffu, ssum, 2);
                l_i[half] = l_i[half] * corr + ssum;

#pragma unroll
                for (int nt = 0; nt < 8; nt++) {
                    o_acc[nt][half * 2 + 0] *= corr;
                    o_acc[nt][half * 2 + 1] *= corr;
                }
            }

            // ---- P to smem: f16x2 key-pairs (warp-private rows) ----
#pragma unroll
            for (int nt = 0; nt < 4; nt++) {
                Ps[warp * 16 + g    ][nt * 4 + tig] = f2h2(s[nt][0], s[nt][1]);
                Ps[warp * 16 + g + 8][nt * 4 + tig] = f2h2(s[nt][2], s[nt][3]);
            }
        }

        __syncthreads();   // Vpk[buf] visible (uniform barrier; Ps warp-private)

        if (active) {
            // ---- O += P @ V ----
#pragma unroll
            for (int kc = 0; kc < 2; kc++) {
                uint32_t af[4];
                af[0] = Ps[warp * 16 + g    ][kc * 8 + tig    ];
                af[1] = Ps[warp * 16 + g + 8][kc * 8 + tig    ];
                af[2] = Ps[warp * 16 + g    ][kc * 8 + tig + 4];
                af[3] = Ps[warp * 16 + g + 8][kc * 8 + tig + 4];
                uint32_t bf[8][2];
#pragma unroll
                for (int nt = 0; nt < 8; nt++) {
                    bf[nt][0] = Vpk[buf][kc * 8 + tig    ][nt * 8 + g];
                    bf[nt][1] = Vpk[buf][kc * 8 + tig + 4][nt * 8 + g];
                }
#pragma unroll
                for (int nt = 0; nt < 8; nt++)
                    mma_f16(o_acc[nt], af, bf[nt]);
            }
        }
    }

    // ---- epilogue: normalize, pack f16x2 pairs along d ----
    uint32_t* Op = g_att + base;
    const float inv0 = 1.0f / l_i[0];
    const float inv1 = 1.0f / l_i[1];
#pragma unroll
    for (int nt = 0; nt < 8; nt++) {
        const int p = nt * 4 + tig;
        Op[(size_t)r_lo * DK2_ + p] = f2h2(o_acc[nt][0] * inv0, o_acc[nt][1] * inv0);
        Op[(size_t)r_hi * DK2_ + p] = f2h2(o_acc[nt][2] * inv1, o_acc[nt][3] * inv1);
    }
}

// ---------------------------------------------------------------------------
// Launch
// ---------------------------------------------------------------------------
extern "C" void kernel_launch(void* const* d_in, const int* in_sizes, int n_in,
                              void* d_out, int out_size) {
    (void)in_sizes; (void)n_in; (void)out_size;
    const float* query = (const float*)d_in[0];
    const float* key   = (const float*)d_in[1];
    const float* value = (const float*)d_in[2];
    const float* Wq = (const float*)d_in[4];
    const float* bq = (const float*)d_in[5];
    const float* Wk = (const float*)d_in[6];
    const float* bk = (const float*)d_in[7];
    const float* Wv = (const float*)d_in[8];
    const float* bv = (const float*)d_in[9];
    const float* Wo = (const float*)d_in[10];
    const float* bo = (const float*)d_in[11];
    float* out = (float*)d_out;

    cvt_inputs <<<dim3(MTOT * D_ / 4 / 256, 3), 256>>>(query, key, value);
    cvt_weights<<<dim3(D2_ * D_ / 4 / 256, 4), 256>>>(Wq, Wk, Wv, Wo);

    dim3 gqkv(D_ / GBN, MTOT / GBM, 3);
    qkv_gemm<<<gqkv, 256>>>(bq, bk, bv);

    attn_tc<<<dim3(S_ / BQ, H_, B_), 256>>>();

    out_gemm<<<dim3(D_ / GBN, MTOT / GBM), 256>>>(bo, out);
}

// round 16
// speedup vs baseline: 1.0953x; 1.0953x over previous
#include <cuda_runtime.h>
#include <math.h>
#include <stdint.h>

// Problem dims (fixed by the dataset)
#define B_   2
#define S_   2048
#define D_   1024
#define D2_  512      // f16x2 pairs per row
#define H_   16
#define DK_  64
#define DK2_ 32
#define MTOT (B_ * S_)
#define NQB  32       // S_/BQ query tiles per (b,h)

// ---------------------------------------------------------------------------
// Scratch (f16x2 pairs stored as uint32)
// ---------------------------------------------------------------------------
__device__ uint32_t g_qin[MTOT * D2_];          // packed inputs [m][k2]
__device__ uint32_t g_kin[MTOT * D2_];
__device__ uint32_t g_vin[MTOT * D2_];
__device__ uint32_t g_q[B_ * H_ * S_ * DK2_];   // head-layout activations (Q pre-scaled by 1/8)
__device__ uint32_t g_k[B_ * H_ * S_ * DK2_];
__device__ uint32_t g_v[B_ * H_ * S_ * DK2_];
__device__ uint32_t g_att[B_ * H_ * S_ * DK2_];
__device__ uint32_t g_wq[D2_ * D_];             // k-pair-packed weights [k2][n]
__device__ uint32_t g_wk[D2_ * D_];
__device__ uint32_t g_wv[D2_ * D_];
__device__ uint32_t g_wo[D2_ * D_];

// f16x2 pack: h0 = lo, h1 = hi
__device__ __forceinline__ uint32_t f2h2(float lo, float hi) {
    uint32_t r;
    asm("cvt.rn.f16x2.f32 %0, %1, %2;" : "=r"(r) : "f"(hi), "f"(lo));
    return r;
}

__device__ __forceinline__ void mma_f16(float* d, const uint32_t* a, const uint32_t* b) {
    asm volatile(
        "mma.sync.aligned.m16n8k16.row.col.f32.f16.f16.f32 "
        "{%0,%1,%2,%3}, {%4,%5,%6,%7}, {%8,%9}, {%0,%1,%2,%3};"
        : "+f"(d[0]), "+f"(d[1]), "+f"(d[2]), "+f"(d[3])
        : "r"(a[0]), "r"(a[1]), "r"(a[2]), "r"(a[3]), "r"(b[0]), "r"(b[1]));
}

__device__ __forceinline__ uint32_t smem_u32(const void* p) {
    return (uint32_t)__cvta_generic_to_shared(p);
}
__device__ __forceinline__ void cp_async16(uint32_t dst, const void* src) {
    asm volatile("cp.async.cg.shared.global [%0], [%1], 16;\n" :: "r"(dst), "l"(src));
}
__device__ __forceinline__ void cp_commit() {
    asm volatile("cp.async.commit_group;\n");
}
template <int N>
__device__ __forceinline__ void cp_wait() {
    asm volatile("cp.async.wait_group %0;\n" :: "n"(N));
}

// ---------------------------------------------------------------------------
// Merged pre-conversion (once per launch).
// z 0..2: inputs (4096 blocks each); z 3..6: weights (512 blocks each).
// ---------------------------------------------------------------------------
__global__ __launch_bounds__(256)
void cvt_all(const float* __restrict__ q, const float* __restrict__ k,
             const float* __restrict__ v,
             const float* __restrict__ wq, const float* __restrict__ wk,
             const float* __restrict__ wv, const float* __restrict__ wo) {
    const int z = blockIdx.y;
    if (z < 3) {
        const float* src = (z == 0) ? q : (z == 1) ? k : v;
        uint32_t*    dst = (z == 0) ? g_qin : (z == 1) ? g_kin : g_vin;
        const int i = blockIdx.x * 256 + threadIdx.x;
        float4 x = ((const float4*)src)[i];
        uint2 o;
        o.x = f2h2(x.x, x.y);
        o.y = f2h2(x.z, x.w);
        ((uint2*)dst)[i] = o;
    } else {
        if (blockIdx.x >= D2_ * D_ / 4 / 256) return;   // 512 blocks needed
        const int zz = z - 3;
        const float* w = (zz == 0) ? wq : (zz == 1) ? wk : (zz == 2) ? wv : wo;
        uint32_t*  dst = (zz == 0) ? g_wq : (zz == 1) ? g_wk : (zz == 2) ? g_wv : g_wo;
        const int idx = blockIdx.x * 256 + threadIdx.x;
        const int k2 = idx >> 8;
        const int n4 = (idx & 255) * 4;
        float4 r0 = *(const float4*)&w[(size_t)(2 * k2)     * D_ + n4];
        float4 r1 = *(const float4*)&w[(size_t)(2 * k2 + 1) * D_ + n4];
        uint4 o;
        o.x = f2h2(r0.x, r1.x);
        o.y = f2h2(r0.y, r1.y);
        o.z = f2h2(r0.z, r1.z);
        o.w = f2h2(r0.w, r1.w);
        *(uint4*)&dst[(size_t)k2 * D_ + n4] = o;
    }
}

// ---------------------------------------------------------------------------
// FP16 GEMM body — R13, plus epilogue output scale (exact power of two).
// ---------------------------------------------------------------------------
#define GBM 128
#define GBN 128
#define GBK2 8
#define AST 12
#define BST 136

template <bool HEAD_OUT>
__device__ __forceinline__ void gemm_body(
    const uint32_t* __restrict__ A, const uint32_t* __restrict__ W,
    const float* __restrict__ bias, void* __restrict__ Cv, float oscale) {

    __shared__ uint32_t As[2][GBM][AST];
    __shared__ uint32_t Bs[2][GBK2][BST];

    const int tid   = threadIdx.x;
    const int wid   = tid >> 5;
    const int lane  = tid & 31;
    const int g     = lane >> 2;
    const int tig   = lane & 3;

    const int warp_m = wid & 3;
    const int warp_n = wid >> 2;

    const int row0 = blockIdx.y * GBM;
    const int col0 = blockIdx.x * GBN;

    const int a_r = tid >> 1, a_c = (tid & 1) * 4;
    const int b_r = tid >> 5, b_c = (tid & 31) * 4;

    auto issue_tile = [&](int kt2, int buf) {
        cp_async16(smem_u32(&As[buf][a_r][a_c]),
                   &A[(size_t)(row0 + a_r) * D2_ + kt2 + a_c]);
        cp_async16(smem_u32(&Bs[buf][b_r][b_c]),
                   &W[(size_t)(kt2 + b_r) * D_ + col0 + b_c]);
        cp_commit();
    };

    float acc[2][8][4];
#pragma unroll
    for (int mt = 0; mt < 2; mt++)
#pragma unroll
        for (int nt = 0; nt < 8; nt++)
#pragma unroll
            for (int i = 0; i < 4; i++) acc[mt][nt][i] = 0.0f;

    const int NT = D2_ / GBK2;
    issue_tile(0, 0);

    for (int it = 0; it < NT; it++) {
        const int buf = it & 1;
        cp_wait<0>();
        __syncthreads();
        if (it + 1 < NT)
            issue_tile((it + 1) * GBK2, buf ^ 1);

        uint32_t afr[2][4], bfr[8][2];
#pragma unroll
        for (int mt = 0; mt < 2; mt++) {
            const int r0 = warp_m * 32 + mt * 16;
            afr[mt][0] = As[buf][r0 + g    ][tig    ];
            afr[mt][1] = As[buf][r0 + g + 8][tig    ];
            afr[mt][2] = As[buf][r0 + g    ][tig + 4];
            afr[mt][3] = As[buf][r0 + g + 8][tig + 4];
        }
#pragma unroll
        for (int nt = 0; nt < 8; nt++) {
            const int n0 = warp_n * 64 + nt * 8;
            bfr[nt][0] = Bs[buf][tig    ][n0 + g];
            bfr[nt][1] = Bs[buf][tig + 4][n0 + g];
        }
#pragma unroll
        for (int mt = 0; mt < 2; mt++)
#pragma unroll
            for (int nt = 0; nt < 8; nt++)
                mma_f16(acc[mt][nt], afr[mt], bfr[nt]);
    }

#pragma unroll
    for (int mt = 0; mt < 2; mt++) {
#pragma unroll
        for (int nt = 0; nt < 8; nt++) {
            const int cbase = col0 + warp_n * 64 + nt * 8 + tig * 2;
#pragma unroll
            for (int half = 0; half < 2; half++) {
                const int r = row0 + warp_m * 32 + mt * 16 + g + half * 8;
                const float v0 = (acc[mt][nt][half * 2 + 0] + bias[cbase])     * oscale;
                const float v1 = (acc[mt][nt][half * 2 + 1] + bias[cbase + 1]) * oscale;
                if (HEAD_OUT) {
                    const int b = r / S_, s = r % S_;
                    const int hh = cbase / DK_, d = cbase % DK_;
                    ((uint32_t*)Cv)[(((size_t)(b * H_ + hh)) * S_ + s) * DK2_ + (d >> 1)] =
                        f2h2(v0, v1);
                } else {
                    ((float*)Cv)[(size_t)r * D_ + cbase    ] = v0;
                    ((float*)Cv)[(size_t)r * D_ + cbase + 1] = v1;
                }
            }
        }
    }
}

__global__ __launch_bounds__(256, 2)
void qkv_gemm(const float* __restrict__ bq, const float* __restrict__ bk,
              const float* __restrict__ bv) {
    const int z = blockIdx.z;
    const uint32_t* A    = (z == 0) ? g_qin : (z == 1) ? g_kin : g_vin;
    const uint32_t* W    = (z == 0) ? g_wq  : (z == 1) ? g_wk  : g_wv;
    const float*    bias = (z == 0) ? bq    : (z == 1) ? bk    : bv;
    uint32_t*       C    = (z == 0) ? g_q   : (z == 1) ? g_k   : g_v;
    // Q pre-scaled by 1/8 = 2^-3 (exact; bitwise-identical to scaling S later)
    gemm_body<true>(A, W, bias, C, (z == 0) ? 0.125f : 1.0f);
}

__global__ __launch_bounds__(256, 2)
void out_gemm(const float* __restrict__ bias, float* __restrict__ C) {
    gemm_body<false>(g_att, g_wo, bias, C, 1.0f);
}

// ---------------------------------------------------------------------------
// FP16 flash attention (causal), R13 per-tile body; balanced pairing:
// CTA p processes q-tile (31-p) then q-tile p -> uniform 33 key blocks/CTA.
// Q pre-scaled, so no scale multiply in softmax.
// ---------------------------------------------------------------------------
#define BQ   64
#define BKA  32
#define KST  36
#define VRST 36
#define VST  72
#define PST  20

__global__ __launch_bounds__(128)
void attn_tc() {
    __shared__ uint32_t Ks[2][BKA][KST];
    __shared__ uint32_t Vraw[2][BKA][VRST];
    __shared__ uint32_t Vpk[2][16][VST];
    __shared__ uint32_t Ps[BQ][PST];

    const int tid  = threadIdx.x;
    const int warp = tid >> 5;
    const int lane = tid & 31;
    const int g    = lane >> 2;
    const int tig  = lane & 3;

    const int p  = blockIdx.x;   // 0..15 (tile pair)
    const int h  = blockIdx.y;
    const int b  = blockIdx.z;
    const size_t base = (size_t)(b * H_ + h) * S_ * DK2_;
    const uint32_t* Kp = g_k + base;
    const uint32_t* Vp = g_v + base;

    auto issue_kv = [&](int kb, int buf) {
        const int k0 = kb * BKA;
#pragma unroll
        for (int i = 0; i < 2; i++) {
            const int idx = tid + i * 128;
            const int r   = idx >> 3;
            const int c4  = (idx & 7) * 4;
            cp_async16(smem_u32(&Ks[buf][r][c4]),   &Kp[(size_t)(k0 + r) * DK2_ + c4]);
            cp_async16(smem_u32(&Vraw[buf][r][c4]), &Vp[(size_t)(k0 + r) * DK2_ + c4]);
        }
        cp_commit();
    };

#pragma unroll 1
    for (int t = 0; t < 2; t++) {
        const int qt = (t == 0) ? (NQB - 1 - p) : p;   // heavy tile first
        const int q0 = qt * BQ;
        const int r_lo = q0 + warp * 16 + g;
        const int r_hi = r_lo + 8;

        // Q fragments (pre-scaled by 1/8 at projection time)
        uint32_t qf[4][4];
        {
            const uint32_t* Qb = g_q + base + (size_t)(q0 + warp * 16) * DK2_;
#pragma unroll
            for (int kc = 0; kc < 4; kc++) {
                qf[kc][0] = Qb[(size_t)g       * DK2_ + kc * 8 + tig    ];
                qf[kc][1] = Qb[(size_t)(g + 8) * DK2_ + kc * 8 + tig    ];
                qf[kc][2] = Qb[(size_t)g       * DK2_ + kc * 8 + tig + 4];
                qf[kc][3] = Qb[(size_t)(g + 8) * DK2_ + kc * 8 + tig + 4];
            }
        }

        float m_i[2] = {-1e30f, -1e30f};
        float l_i[2] = {0.0f, 0.0f};
        float o_acc[8][4];
#pragma unroll
        for (int nt = 0; nt < 8; nt++)
#pragma unroll
            for (int i = 0; i < 4; i++) o_acc[nt][i] = 0.0f;

        const int nkb = (q0 + BQ) / BKA;
        issue_kv(0, 0);

        for (int kb = 0; kb < nkb; kb++) {
            const int k0  = kb * BKA;
            const int buf = kb & 1;
            cp_wait<0>();
            __syncthreads();
            if (kb + 1 < nkb)
                issue_kv(kb + 1, buf ^ 1);

            // ---- repack V: d-packed -> key-pair-packed ----
#pragma unroll
            for (int i = 0; i < 4; i++) {
                const int c  = tid + i * 128;
                const int k2 = c >> 5, d2 = c & 31;
                const uint32_t lo = Vraw[buf][2 * k2    ][d2];
                const uint32_t hi = Vraw[buf][2 * k2 + 1][d2];
                uint32_t e, o;
                asm("prmt.b32 %0, %1, %2, 0x5410;" : "=r"(e) : "r"(lo), "r"(hi));
                asm("prmt.b32 %0, %1, %2, 0x7632;" : "=r"(o) : "r"(lo), "r"(hi));
                Vpk[buf][k2][2 * d2    ] = e;
                Vpk[buf][k2][2 * d2 + 1] = o;
            }

            // ---- S = Q @ K^T ----
            float s[4][4];
#pragma unroll
            for (int nt = 0; nt < 4; nt++)
#pragma unroll
                for (int i = 0; i < 4; i++) s[nt][i] = 0.0f;

#pragma unroll
            for (int kc = 0; kc < 4; kc++) {
                uint32_t bf[4][2];
#pragma unroll
                for (int nt = 0; nt < 4; nt++) {
                    bf[nt][0] = Ks[buf][nt * 8 + g][kc * 8 + tig    ];
                    bf[nt][1] = Ks[buf][nt * 8 + g][kc * 8 + tig + 4];
                }
#pragma unroll
                for (int nt = 0; nt < 4; nt++)
                    mma_f16(s[nt], qf[kc], bf[nt]);
            }

            // ---- causal mask + online softmax (scale already in Q) ----
#pragma unroll
            for (int half = 0; half < 2; half++) {
                const int qg = (half == 0) ? r_lo : r_hi;
                float mx = -1e30f;
#pragma unroll
                for (int nt = 0; nt < 4; nt++) {
#pragma unroll
                    for (int cc = 0; cc < 2; cc++) {
                        const int kg = k0 + nt * 8 + tig * 2 + cc;
                        float sv = s[nt][half * 2 + cc];
                        if (kg > qg) sv = -1e30f;
                        s[nt][half * 2 + cc] = sv;
                        mx = fmaxf(mx, sv);
                    }
                }
                mx = fmaxf(mx, __shfl_xor_sync(0xffffffffu, mx, 1));
                mx = fmaxf(mx, __shfl_xor_sync(0xffffffffu, mx, 2));

                const float mnew = fmaxf(m_i[half], mx);
                const float corr = __expf(m_i[half] - mnew);
                m_i[half] = mnew;

                float ssum = 0.0f;
#pragma unroll
                for (int nt = 0; nt < 4; nt++) {
#pragma unroll
                    for (int cc = 0; cc < 2; cc++) {
                        const float pp = __expf(s[nt][half * 2 + cc] - mnew);
                        s[nt][half * 2 + cc] = pp;
                        ssum += pp;
                    }
                }
                ssum += __shfl_xor_sync(0xffffffffu, ssum, 1);
                ssum += __shfl_xor_sync(0xffffffffu, ssum, 2);
                l_i[half] = l_i[half] * corr + ssum;

#pragma unroll
                for (int nt = 0; nt < 8; nt++) {
                    o_acc[nt][half * 2 + 0] *= corr;
                    o_acc[nt][half * 2 + 1] *= corr;
                }
            }

            // ---- P to smem: f16x2 key-pairs ----
#pragma unroll
            for (int nt = 0; nt < 4; nt++) {
                Ps[warp * 16 + g    ][nt * 4 + tig] = f2h2(s[nt][0], s[nt][1]);
                Ps[warp * 16 + g + 8][nt * 4 + tig] = f2h2(s[nt][2], s[nt][3]);
            }
            __syncthreads();

            // ---- O += P @ V ----
#pragma unroll
            for (int kc = 0; kc < 2; kc++) {
                uint32_t af[4];
                af[0] = Ps[warp * 16 + g    ][kc * 8 + tig    ];
                af[1] = Ps[warp * 16 + g + 8][kc * 8 + tig    ];
                af[2] = Ps[warp * 16 + g    ][kc * 8 + tig + 4];
                af[3] = Ps[warp * 16 + g + 8][kc * 8 + tig + 4];
                uint32_t bf[8][2];
#pragma unroll
                for (int nt = 0; nt < 8; nt++) {
                    bf[nt][0] = Vpk[buf][kc * 8 + tig    ][nt * 8 + g];
                    bf[nt][1] = Vpk[buf][kc * 8 + tig + 4][nt * 8 + g];
                }
#pragma unroll
                for (int nt = 0; nt < 8; nt++)
                    mma_f16(o_acc[nt], af, bf[nt]);
            }
        }

        // ---- epilogue for this tile ----
        uint32_t* Op = g_att + base;
        const float inv0 = 1.0f / l_i[0];
        const float inv1 = 1.0f / l_i[1];
#pragma unroll
        for (int nt = 0; nt < 8; nt++) {
            const int pp = nt * 4 + tig;
            Op[(size_t)r_lo * DK2_ + pp] = f2h2(o_acc[nt][0] * inv0, o_acc[nt][1] * inv0);
            Op[(size_t)r_hi * DK2_ + pp] = f2h2(o_acc[nt][2] * inv1, o_acc[nt][3] * inv1);
        }

        __syncthreads();   // all reads of K/V/P buffers done before next tile reuses them
    }
}

// ---------------------------------------------------------------------------
// Launch
// ---------------------------------------------------------------------------
extern "C" void kernel_launch(void* const* d_in, const int* in_sizes, int n_in,
                              void* d_out, int out_size) {
    (void)in_sizes; (void)n_in; (void)out_size;
    const float* query = (const float*)d_in[0];
    const float* key   = (const float*)d_in[1];
    const float* value = (const float*)d_in[2];
    const float* Wq = (const float*)d_in[4];
    const float* bq = (const float*)d_in[5];
    const float* Wk = (const float*)d_in[6];
    const float* bk = (const float*)d_in[7];
    const float* Wv = (const float*)d_in[8];
    const float* bv = (const float*)d_in[9];
    const float* Wo = (const float*)d_in[10];
    const float* bo = (const float*)d_in[11];
    float* out = (float*)d_out;

    cvt_all<<<dim3(MTOT * D_ / 4 / 256, 7), 256>>>(query, key, value, Wq, Wk, Wv, Wo);

    dim3 gqkv(D_ / GBN, MTOT / GBM, 3);
    qkv_gemm<<<gqkv, 256>>>(bq, bk, bv);

    attn_tc<<<dim3(NQB / 2, H_, B_), 128>>>();

    out_gemm<<<dim3(D_ / GBN, MTOT / GBM), 256>>>(bo, out);
}

// round 17
// speedup vs baseline: 1.1063x; 1.0100x over previous
#include <cuda_runtime.h>
#include <math.h>
#include <stdint.h>

// Problem dims (fixed by the dataset)
#define B_   2
#define S_   2048
#define D_   1024
#define D2_  512      // f16x2 pairs per row
#define H_   16
#define DK_  64
#define DK2_ 32
#define MTOT (B_ * S_)
#define NQB  32       // S_/BQ query tiles per (b,h)

// ---------------------------------------------------------------------------
// Scratch (f16x2 pairs stored as uint32)
// ---------------------------------------------------------------------------
__device__ uint32_t g_qin[MTOT * D2_];          // packed inputs [m][k2]
__device__ uint32_t g_kin[MTOT * D2_];
__device__ uint32_t g_vin[MTOT * D2_];
__device__ uint32_t g_q[B_ * H_ * S_ * DK2_];   // head-layout activations (Q pre-scaled by 1/8)
__device__ uint32_t g_k[B_ * H_ * S_ * DK2_];
__device__ uint32_t g_v[B_ * H_ * S_ * DK2_];
__device__ uint32_t g_att[B_ * H_ * S_ * DK2_];
__device__ uint32_t g_wq[D2_ * D_];             // k-pair-packed weights [k2][n]
__device__ uint32_t g_wk[D2_ * D_];
__device__ uint32_t g_wv[D2_ * D_];
__device__ uint32_t g_wo[D2_ * D_];

// f16x2 pack: h0 = lo, h1 = hi
__device__ __forceinline__ uint32_t f2h2(float lo, float hi) {
    uint32_t r;
    asm("cvt.rn.f16x2.f32 %0, %1, %2;" : "=r"(r) : "f"(hi), "f"(lo));
    return r;
}

__device__ __forceinline__ void mma_f16(float* d, const uint32_t* a, const uint32_t* b) {
    asm volatile(
        "mma.sync.aligned.m16n8k16.row.col.f32.f16.f16.f32 "
        "{%0,%1,%2,%3}, {%4,%5,%6,%7}, {%8,%9}, {%0,%1,%2,%3};"
        : "+f"(d[0]), "+f"(d[1]), "+f"(d[2]), "+f"(d[3])
        : "r"(a[0]), "r"(a[1]), "r"(a[2]), "r"(a[3]), "r"(b[0]), "r"(b[1]));
}

__device__ __forceinline__ uint32_t smem_u32(const void* p) {
    return (uint32_t)__cvta_generic_to_shared(p);
}
__device__ __forceinline__ void cp_async16(uint32_t dst, const void* src) {
    asm volatile("cp.async.cg.shared.global [%0], [%1], 16;\n" :: "r"(dst), "l"(src));
}
__device__ __forceinline__ void cp_commit() {
    asm volatile("cp.async.commit_group;\n");
}
template <int N>
__device__ __forceinline__ void cp_wait() {
    asm volatile("cp.async.wait_group %0;\n" :: "n"(N));
}

// ---------------------------------------------------------------------------
// Merged pre-conversion (once per launch) — unchanged from R16
// ---------------------------------------------------------------------------
__global__ __launch_bounds__(256)
void cvt_all(const float* __restrict__ q, const float* __restrict__ k,
             const float* __restrict__ v,
             const float* __restrict__ wq, const float* __restrict__ wk,
             const float* __restrict__ wv, const float* __restrict__ wo) {
    const int z = blockIdx.y;
    if (z < 3) {
        const float* src = (z == 0) ? q : (z == 1) ? k : v;
        uint32_t*    dst = (z == 0) ? g_qin : (z == 1) ? g_kin : g_vin;
        const int i = blockIdx.x * 256 + threadIdx.x;
        float4 x = ((const float4*)src)[i];
        uint2 o;
        o.x = f2h2(x.x, x.y);
        o.y = f2h2(x.z, x.w);
        ((uint2*)dst)[i] = o;
    } else {
        if (blockIdx.x >= D2_ * D_ / 4 / 256) return;
        const int zz = z - 3;
        const float* w = (zz == 0) ? wq : (zz == 1) ? wk : (zz == 2) ? wv : wo;
        uint32_t*  dst = (zz == 0) ? g_wq : (zz == 1) ? g_wk : (zz == 2) ? g_wv : g_wo;
        const int idx = blockIdx.x * 256 + threadIdx.x;
        const int k2 = idx >> 8;
        const int n4 = (idx & 255) * 4;
        float4 r0 = *(const float4*)&w[(size_t)(2 * k2)     * D_ + n4];
        float4 r1 = *(const float4*)&w[(size_t)(2 * k2 + 1) * D_ + n4];
        uint4 o;
        o.x = f2h2(r0.x, r1.x);
        o.y = f2h2(r0.y, r1.y);
        o.z = f2h2(r0.z, r1.z);
        o.w = f2h2(r0.w, r1.w);
        *(uint4*)&dst[(size_t)k2 * D_ + n4] = o;
    }
}

// ---------------------------------------------------------------------------
// FP16 GEMM body: 4-stage cp.async pipeline (3 tiles in flight).
// Numerics identical to R16 (same mma order, same cvt placement).
// ---------------------------------------------------------------------------
#define GBM 128
#define GBN 128
#define GBK2 8
#define AST 12    // A-frag banks (12g+tig(+4)) distinct
#define BST 136   // B-frag banks (8tig+g) distinct
#define NSTG 4

template <bool HEAD_OUT>
__device__ __forceinline__ void gemm_body(
    const uint32_t* __restrict__ A, const uint32_t* __restrict__ W,
    const float* __restrict__ bias, void* __restrict__ Cv, float oscale) {

    __shared__ uint32_t As[NSTG][GBM][AST];   // 24576 B
    __shared__ uint32_t Bs[NSTG][GBK2][BST];  // 17408 B (41984 total)

    const int tid   = threadIdx.x;
    const int wid   = tid >> 5;
    const int lane  = tid & 31;
    const int g     = lane >> 2;
    const int tig   = lane & 3;

    const int warp_m = wid & 3;
    const int warp_n = wid >> 2;

    const int row0 = blockIdx.y * GBM;
    const int col0 = blockIdx.x * GBN;

    const int a_r = tid >> 1, a_c = (tid & 1) * 4;
    const int b_r = tid >> 5, b_c = (tid & 31) * 4;

    auto issue_tile = [&](int it) {
        const int kt2 = it * GBK2;
        const int buf = it & (NSTG - 1);
        cp_async16(smem_u32(&As[buf][a_r][a_c]),
                   &A[(size_t)(row0 + a_r) * D2_ + kt2 + a_c]);
        cp_async16(smem_u32(&Bs[buf][b_r][b_c]),
                   &W[(size_t)(kt2 + b_r) * D_ + col0 + b_c]);
        cp_commit();
    };

    float acc[2][8][4];
#pragma unroll
    for (int mt = 0; mt < 2; mt++)
#pragma unroll
        for (int nt = 0; nt < 8; nt++)
#pragma unroll
            for (int i = 0; i < 4; i++) acc[mt][nt][i] = 0.0f;

    const int NT = D2_ / GBK2;   // 64 tiles
    issue_tile(0);
    issue_tile(1);
    issue_tile(2);

    for (int it = 0; it < NT; it++) {
        const int buf = it & (NSTG - 1);
        // 3 groups outstanding max; wait until <=2 -> tile `it` resident
        cp_wait<2>();
        __syncthreads();   // also: all warps done computing tile it-1 -> its buf free
        if (it + 3 < NT)
            issue_tile(it + 3);   // writes buf (it+3)&3 == (it-1)&3 (free)

        uint32_t afr[2][4], bfr[8][2];
#pragma unroll
        for (int mt = 0; mt < 2; mt++) {
            const int r0 = warp_m * 32 + mt * 16;
            afr[mt][0] = As[buf][r0 + g    ][tig    ];
            afr[mt][1] = As[buf][r0 + g + 8][tig    ];
            afr[mt][2] = As[buf][r0 + g    ][tig + 4];
            afr[mt][3] = As[buf][r0 + g + 8][tig + 4];
        }
#pragma unroll
        for (int nt = 0; nt < 8; nt++) {
            const int n0 = warp_n * 64 + nt * 8;
            bfr[nt][0] = Bs[buf][tig    ][n0 + g];
            bfr[nt][1] = Bs[buf][tig + 4][n0 + g];
        }
#pragma unroll
        for (int mt = 0; mt < 2; mt++)
#pragma unroll
            for (int nt = 0; nt < 8; nt++)
                mma_f16(acc[mt][nt], afr[mt], bfr[nt]);
    }

#pragma unroll
    for (int mt = 0; mt < 2; mt++) {
#pragma unroll
        for (int nt = 0; nt < 8; nt++) {
            const int cbase = col0 + warp_n * 64 + nt * 8 + tig * 2;
#pragma unroll
            for (int half = 0; half < 2; half++) {
                const int r = row0 + warp_m * 32 + mt * 16 + g + half * 8;
                const float v0 = (acc[mt][nt][half * 2 + 0] + bias[cbase])     * oscale;
                const float v1 = (acc[mt][nt][half * 2 + 1] + bias[cbase + 1]) * oscale;
                if (HEAD_OUT) {
                    const int b = r / S_, s = r % S_;
                    const int hh = cbase / DK_, d = cbase % DK_;
                    ((uint32_t*)Cv)[(((size_t)(b * H_ + hh)) * S_ + s) * DK2_ + (d >> 1)] =
                        f2h2(v0, v1);
                } else {
                    ((float*)Cv)[(size_t)r * D_ + cbase    ] = v0;
                    ((float*)Cv)[(size_t)r * D_ + cbase + 1] = v1;
                }
            }
        }
    }
}

__global__ __launch_bounds__(256, 2)
void qkv_gemm(const float* __restrict__ bq, const float* __restrict__ bk,
              const float* __restrict__ bv) {
    const int z = blockIdx.z;
    const uint32_t* A    = (z == 0) ? g_qin : (z == 1) ? g_kin : g_vin;
    const uint32_t* W    = (z == 0) ? g_wq  : (z == 1) ? g_wk  : g_wv;
    const float*    bias = (z == 0) ? bq    : (z == 1) ? bk    : bv;
    uint32_t*       C    = (z == 0) ? g_q   : (z == 1) ? g_k   : g_v;
    // Q pre-scaled by 1/8 = 2^-3 (exact; bitwise-identical to scaling S later)
    gemm_body<true>(A, W, bias, C, (z == 0) ? 0.125f : 1.0f);
}

__global__ __launch_bounds__(256, 2)
void out_gemm(const float* __restrict__ bias, float* __restrict__ C) {
    gemm_body<false>(g_att, g_wo, bias, C, 1.0f);
}

// ---------------------------------------------------------------------------
// FP16 flash attention (causal) — R16 version verbatim (balanced pairing).
// ---------------------------------------------------------------------------
#define BQ   64
#define BKA  32
#define KST  36
#define VRST 36
#define VST  72
#define PST  20

__global__ __launch_bounds__(128)
void attn_tc() {
    __shared__ uint32_t Ks[2][BKA][KST];
    __shared__ uint32_t Vraw[2][BKA][VRST];
    __shared__ uint32_t Vpk[2][16][VST];
    __shared__ uint32_t Ps[BQ][PST];

    const int tid  = threadIdx.x;
    const int warp = tid >> 5;
    const int lane = tid & 31;
    const int g    = lane >> 2;
    const int tig  = lane & 3;

    const int p  = blockIdx.x;   // 0..15 (tile pair)
    const int h  = blockIdx.y;
    const int b  = blockIdx.z;
    const size_t base = (size_t)(b * H_ + h) * S_ * DK2_;
    const uint32_t* Kp = g_k + base;
    const uint32_t* Vp = g_v + base;

    auto issue_kv = [&](int kb, int buf) {
        const int k0 = kb * BKA;
#pragma unroll
        for (int i = 0; i < 2; i++) {
            const int idx = tid + i * 128;
            const int r   = idx >> 3;
            const int c4  = (idx & 7) * 4;
            cp_async16(smem_u32(&Ks[buf][r][c4]),   &Kp[(size_t)(k0 + r) * DK2_ + c4]);
            cp_async16(smem_u32(&Vraw[buf][r][c4]), &Vp[(size_t)(k0 + r) * DK2_ + c4]);
        }
        cp_commit();
    };

#pragma unroll 1
    for (int t = 0; t < 2; t++) {
        const int qt = (t == 0) ? (NQB - 1 - p) : p;   // heavy tile first
        const int q0 = qt * BQ;
        const int r_lo = q0 + warp * 16 + g;
        const int r_hi = r_lo + 8;

        uint32_t qf[4][4];
        {
            const uint32_t* Qb = g_q + base + (size_t)(q0 + warp * 16) * DK2_;
#pragma unroll
            for (int kc = 0; kc < 4; kc++) {
                qf[kc][0] = Qb[(size_t)g       * DK2_ + kc * 8 + tig    ];
                qf[kc][1] = Qb[(size_t)(g + 8) * DK2_ + kc * 8 + tig    ];
                qf[kc][2] = Qb[(size_t)g       * DK2_ + kc * 8 + tig + 4];
                qf[kc][3] = Qb[(size_t)(g + 8) * DK2_ + kc * 8 + tig + 4];
            }
        }

        float m_i[2] = {-1e30f, -1e30f};
        float l_i[2] = {0.0f, 0.0f};
        float o_acc[8][4];
#pragma unroll
        for (int nt = 0; nt < 8; nt++)
#pragma unroll
            for (int i = 0; i < 4; i++) o_acc[nt][i] = 0.0f;

        const int nkb = (q0 + BQ) / BKA;
        issue_kv(0, 0);

        for (int kb = 0; kb < nkb; kb++) {
            const int k0  = kb * BKA;
            const int buf = kb & 1;
            cp_wait<0>();
            __syncthreads();
            if (kb + 1 < nkb)
                issue_kv(kb + 1, buf ^ 1);

#pragma unroll
            for (int i = 0; i < 4; i++) {
                const int c  = tid + i * 128;
                const int k2 = c >> 5, d2 = c & 31;
                const uint32_t lo = Vraw[buf][2 * k2    ][d2];
                const uint32_t hi = Vraw[buf][2 * k2 + 1][d2];
                uint32_t e, o;
                asm("prmt.b32 %0, %1, %2, 0x5410;" : "=r"(e) : "r"(lo), "r"(hi));
                asm("prmt.b32 %0, %1, %2, 0x7632;" : "=r"(o) : "r"(lo), "r"(hi));
                Vpk[buf][k2][2 * d2    ] = e;
                Vpk[buf][k2][2 * d2 + 1] = o;
            }

            float s[4][4];
#pragma unroll
            for (int nt = 0; nt < 4; nt++)
#pragma unroll
                for (int i = 0; i < 4; i++) s[nt][i] = 0.0f;

#pragma unroll
            for (int kc = 0; kc < 4; kc++) {
                uint32_t bf[4][2];
#pragma unroll
                for (int nt = 0; nt < 4; nt++) {
                    bf[nt][0] = Ks[buf][nt * 8 + g][kc * 8 + tig    ];
                    bf[nt][1] = Ks[buf][nt * 8 + g][kc * 8 + tig + 4];
                }
#pragma unroll
                for (int nt = 0; nt < 4; nt++)
                    mma_f16(s[nt], qf[kc], bf[nt]);
            }

#pragma unroll
            for (int half = 0; half < 2; half++) {
                const int qg = (half == 0) ? r_lo : r_hi;
                float mx = -1e30f;
#pragma unroll
                for (int nt = 0; nt < 4; nt++) {
#pragma unroll
                    for (int cc = 0; cc < 2; cc++) {
                        const int kg = k0 + nt * 8 + tig * 2 + cc;
                        float sv = s[nt][half * 2 + cc];
                        if (kg > qg) sv = -1e30f;
                        s[nt][half * 2 + cc] = sv;
                        mx = fmaxf(mx, sv);
                    }
                }
                mx = fmaxf(mx, __shfl_xor_sync(0xffffffffu, mx, 1));
                mx = fmaxf(mx, __shfl_xor_sync(0xffffffffu, mx, 2));

                const float mnew = fmaxf(m_i[half], mx);
                const float corr = __expf(m_i[half] - mnew);
                m_i[half] = mnew;

                float ssum = 0.0f;
#pragma unroll
                for (int nt = 0; nt < 4; nt++) {
#pragma unroll
                    for (int cc = 0; cc < 2; cc++) {
                        const float pp = __expf(s[nt][half * 2 + cc] - mnew);
                        s[nt][half * 2 + cc] = pp;
                        ssum += pp;
                    }
                }
                ssum += __shfl_xor_sync(0xffffffffu, ssum, 1);
                ssum += __shfl_xor_sync(0xffffffffu, ssum, 2);
                l_i[half] = l_i[half] * corr + ssum;

#pragma unroll
                for (int nt = 0; nt < 8; nt++) {
                    o_acc[nt][half * 2 + 0] *= corr;
                    o_acc[nt][half * 2 + 1] *= corr;
                }
            }

#pragma unroll
            for (int nt = 0; nt < 4; nt++) {
                Ps[warp * 16 + g    ][nt * 4 + tig] = f2h2(s[nt][0], s[nt][1]);
                Ps[warp * 16 + g + 8][nt * 4 + tig] = f2h2(s[nt][2], s[nt][3]);
            }
            __syncthreads();

#pragma unroll
            for (int kc = 0; kc < 2; kc++) {
                uint32_t af[4];
                af[0] = Ps[warp * 16 + g    ][kc * 8 + tig    ];
                af[1] = Ps[warp * 16 + g + 8][kc * 8 + tig    ];
                af[2] = Ps[warp * 16 + g    ][kc * 8 + tig + 4];
                af[3] = Ps[warp * 16 + g + 8][kc * 8 + tig + 4];
                uint32_t bf[8][2];
#pragma unroll
                for (int nt = 0; nt < 8; nt++) {
                    bf[nt][0] = Vpk[buf][kc * 8 + tig    ][nt * 8 + g];
                    bf[nt][1] = Vpk[buf][kc * 8 + tig + 4][nt * 8 + g];
                }
#pragma unroll
                for (int nt = 0; nt < 8; nt++)
                    mma_f16(o_acc[nt], af, bf[nt]);
            }
        }

        uint32_t* Op = g_att + base;
        const float inv0 = 1.0f / l_i[0];
        const float inv1 = 1.0f / l_i[1];
#pragma unroll
        for (int nt = 0; nt < 8; nt++) {
            const int pp = nt * 4 + tig;
            Op[(size_t)r_lo * DK2_ + pp] = f2h2(o_acc[nt][0] * inv0, o_acc[nt][1] * inv0);
            Op[(size_t)r_hi * DK2_ + pp] = f2h2(o_acc[nt][2] * inv1, o_acc[nt][3] * inv1);
        }

        __syncthreads();
    }
}

// ---------------------------------------------------------------------------
// Launch
// ---------------------------------------------------------------------------
extern "C" void kernel_launch(void* const* d_in, const int* in_sizes, int n_in,
                              void* d_out, int out_size) {
    (void)in_sizes; (void)n_in; (void)out_size;
    const float* query = (const float*)d_in[0];
    const float* key   = (const float*)d_in[1];
    const float* value = (const float*)d_in[2];
    const float* Wq = (const float*)d_in[4];
    const float* bq = (const float*)d_in[5];
    const float* Wk = (const float*)d_in[6];
    const float* bk = (const float*)d_in[7];
    const float* Wv = (const float*)d_in[8];
    const float* bv = (const float*)d_in[9];
    const float* Wo = (const float*)d_in[10];
    const float* bo = (const float*)d_in[11];
    float* out = (float*)d_out;

    cvt_all<<<dim3(MTOT * D_ / 4 / 256, 7), 256>>>(query, key, value, Wq, Wk, Wv, Wo);

    dim3 gqkv(D_ / GBN, MTOT / GBM, 3);
    qkv_gemm<<<gqkv, 256>>>(bq, bk, bv);

    attn_tc<<<dim3(NQB / 2, H_, B_), 128>>>();

    out_gemm<<<dim3(D_ / GBN, MTOT / GBM), 256>>>(bo, out);
}